// round 17
// baseline (speedup 1.0000x reference)
#include <cuda_runtime.h>
#include <cuda_bf16.h>
#include <cstdint>

#define N_NODES 10000
#define N_EDGES 160000

// ---------------- scratch ----------------
// feat per node (320): [0:128) feat0[u]; [128:320) feat1[u][i] (i fastest)
// self: same layout, pre-scaled by cos(angle)
// g_h: row-major [e][k], k in 0..63
// g_agg per node (768): [0:128) mid0a | [128:192) mid0b | [192:576) mid1a SoA (192+i*128+u) | [576:768) mid1b SoA (576+i*64+u)
__device__ __align__(16) float g_feat[N_NODES * 320];
__device__ __align__(16) float g_self[N_NODES * 320];
__device__ __align__(16) float g_h[(size_t)N_EDGES * 64];
__device__ __align__(16) float g_agg[N_NODES * 768];
// Wcat transposed, bf16 split: [j][k], j in 0..383 (scales folded)
__device__ __align__(16) __nv_bfloat16 g_Wt_hi[384 * 64];
__device__ __align__(16) __nv_bfloat16 g_Wt_lo[384 * 64];

#define AGG_F4   ((N_NODES * 768) / 4)    // 1,920,000 float4
#define ZERO_BLK ((AGG_F4 + 1023) / 1024) // 1875 blocks of 1024 float4

__device__ __forceinline__ float gelu_tanh(float x) {
    float x3 = x * x * x;
    return 0.5f * x * (1.0f + tanhf(0.7978845608028654f * (x + 0.044715f * x3)));
}

__device__ __forceinline__ void red4(float* p, float a, float b, float c, float d) {
    asm volatile("red.global.add.v4.f32 [%0], {%1,%2,%3,%4};"
                 :: "l"(p), "f"(a), "f"(b), "f"(c), "f"(d) : "memory");
}

__device__ __forceinline__ uint32_t smem_u32(const void* p) {
    uint32_t a;
    asm("{ .reg .u64 t; cvta.to.shared.u64 t, %1; cvt.u32.u64 %0, t; }" : "=r"(a) : "l"(p));
    return a;
}
__device__ __forceinline__ void ldsm4(uint32_t* r, uint32_t addr) {
    asm volatile("ldmatrix.sync.aligned.m8n8.x4.shared.b16 {%0,%1,%2,%3}, [%4];"
                 : "=r"(r[0]), "=r"(r[1]), "=r"(r[2]), "=r"(r[3]) : "r"(addr));
}
__device__ __forceinline__ void mma_bf16(float* c, const uint32_t* a,
                                         uint32_t b0, uint32_t b1) {
    asm volatile(
        "mma.sync.aligned.m16n8k16.row.col.f32.bf16.bf16.f32 "
        "{%0,%1,%2,%3}, {%4,%5,%6,%7}, {%8,%9}, {%0,%1,%2,%3};"
        : "+f"(c[0]), "+f"(c[1]), "+f"(c[2]), "+f"(c[3])
        : "r"(a[0]), "r"(a[1]), "r"(a[2]), "r"(a[3]), "r"(b0), "r"(b1));
}
__device__ __forceinline__ uint32_t swz(uint32_t off) {
    return off ^ ((off >> 3) & 0x70);
}

// ---------------- kernel 1: node pre (streaming-W GEMMs) + fused agg-zero ----------------
__global__ __launch_bounds__(256) void node_pre_kernel(const float* __restrict__ node_input,
                                const float* __restrict__ Wa0,
                                const float* __restrict__ Wa1,
                                const float* __restrict__ Wb0,
                                const float* __restrict__ Wb1) {
    extern __shared__ float sm[];
    const int tid = threadIdx.x;
    const float sA0 = 0.08838834764831845f;            // 1/sqrt(128)
    const float sA1 = 0.125f;                          // 1/sqrt(64)
    const float cc  = 0.9238795325112867f;             // cos(pi/8)

    if (blockIdx.x >= 1250) {
        float4* p = (float4*)g_agg;
        int base = (blockIdx.x - 1250) * 1024 + tid;
        #pragma unroll
        for (int r = 0; r < 4; r++) {
            int i = base + r * 256;
            if (i < AGG_F4)
                p[i] = make_float4(0.f, 0.f, 0.f, 0.f);
        }
        return;
    }

    if (blockIdx.x < 625) {
        const int nb = blockIdx.x * 16;
        float* xs0 = sm;                               // 16 x 128
        for (int i = tid; i < 16 * 128; i += 256)
            xs0[i] = node_input[(size_t)(nb + (i >> 7)) * 320 + (i & 127)];
        __syncthreads();

        const int sel = tid >> 7;
        const int u   = tid & 127;
        const float* W = sel ? Wb0 : Wa0;
        const float sc = sel ? (cc * sA0) : sA0;
        float acc[16];
        #pragma unroll
        for (int n = 0; n < 16; n++) acc[n] = 0.f;
        #pragma unroll 2
        for (int v = 0; v < 128; v += 4) {
            float w0 = W[(v + 0) * 128 + u];
            float w1 = W[(v + 1) * 128 + u];
            float w2 = W[(v + 2) * 128 + u];
            float w3 = W[(v + 3) * 128 + u];
            #pragma unroll
            for (int n = 0; n < 16; n++) {
                float4 xq = *(const float4*)&xs0[n * 128 + v];
                acc[n] = fmaf(xq.x, w0, acc[n]);
                acc[n] = fmaf(xq.y, w1, acc[n]);
                acc[n] = fmaf(xq.z, w2, acc[n]);
                acc[n] = fmaf(xq.w, w3, acc[n]);
            }
        }
        float* dst = sel ? g_self : g_feat;
        #pragma unroll
        for (int n = 0; n < 16; n++)
            dst[(size_t)(nb + n) * 320 + u] = acc[n] * sc;
    } else {
        const int nb = (blockIdx.x - 625) * 16;
        float* xs1 = sm;                               // 16 x 3 x 64
        for (int idx = tid; idx < 16 * 192; idx += 256) {
            int n = idx / 192, r = idx % 192;
            int i = r >> 6, v = r & 63;
            xs1[idx] = node_input[(size_t)(nb + n) * 320 + 128 + v * 3 + i];
        }
        __syncthreads();

        const int nh  = tid >> 7;
        const int lcl = tid & 127;
        const int sel = lcl >> 6;
        const int u   = lcl & 63;
        const float* W = sel ? Wb1 : Wa1;
        const float sc = sel ? (cc * sA1) : sA1;
        float acc[8][3];
        #pragma unroll
        for (int n = 0; n < 8; n++)
            #pragma unroll
            for (int i = 0; i < 3; i++) acc[n][i] = 0.f;
        #pragma unroll 2
        for (int v = 0; v < 64; v += 4) {
            float w0 = W[(v + 0) * 64 + u];
            float w1 = W[(v + 1) * 64 + u];
            float w2 = W[(v + 2) * 64 + u];
            float w3 = W[(v + 3) * 64 + u];
            #pragma unroll
            for (int n = 0; n < 8; n++) {
                const float* xb = &xs1[(nh * 8 + n) * 192 + v];
                #pragma unroll
                for (int i = 0; i < 3; i++) {
                    float4 xq = *(const float4*)&xb[i * 64];
                    acc[n][i] = fmaf(xq.x, w0, acc[n][i]);
                    acc[n][i] = fmaf(xq.y, w1, acc[n][i]);
                    acc[n][i] = fmaf(xq.z, w2, acc[n][i]);
                    acc[n][i] = fmaf(xq.w, w3, acc[n][i]);
                }
            }
        }
        float* dst = sel ? g_self : g_feat;
        #pragma unroll
        for (int n = 0; n < 8; n++)
            #pragma unroll
            for (int i = 0; i < 3; i++)
                dst[(size_t)(nb + nh * 8 + n) * 320 + 128 + u * 3 + i] = acc[n][i] * sc;
    }
}

// ---------------- kernel 1b: Wcat transpose + bf16 hi/lo split ----------------
__global__ __launch_bounds__(256) void wt_prep_kernel(const float* __restrict__ Wtp0,
                               const float* __restrict__ Wtp1,
                               const float* __restrict__ Wtp2,
                               const float* __restrict__ Wtp3) {
    int idx = blockIdx.x * 256 + threadIdx.x;
    if (idx >= 384 * 64) return;
    int j = idx >> 6, k = idx & 63;
    const float f0 = 0.03125f;                        // (1/8)*(1/4)
    const float f3 = 0.03125f * 0.5773502691896258f;  // * 1/sqrt(3)
    float w;
    if (j < 128)      w = Wtp0[k * 128 + j] * f0;
    else if (j < 256) w = Wtp1[k * 128 + (j - 128)] * f0;
    else if (j < 320) w = Wtp2[k * 64 + (j - 256)] * f0;
    else              w = Wtp3[k * 64 + (j - 320)] * f3;
    __nv_bfloat16 hi = __float2bfloat16(w);
    float lo = w - __bfloat162float(hi);
    g_Wt_hi[idx] = hi;
    g_Wt_lo[idx] = __float2bfloat16(lo);
}

// ---------------- kernel 2: edge MLP (h row-major out) ----------------
__global__ __launch_bounds__(256) void edge_mlp_kernel(const float* __restrict__ es_attr,
                                const float* __restrict__ M1,
                                const float* __restrict__ M2) {
    __shared__ float sM1[8 * 64];
    __shared__ float sM2[64 * 64];
    const int tid = threadIdx.x;
    const float s1 = 0.3535533905932738f;  // 1/sqrt(8)
    const float s2 = 0.125f;
    for (int i = tid; i < 512; i += 256)  sM1[i] = M1[i] * s1;
    for (int i = tid; i < 4096; i += 256) sM2[i] = M2[i] * s2;
    __syncthreads();

    const int e = blockIdx.x * 256 + tid;
    float* hout = g_h + (size_t)e * 64;
    float es[8];
    {
        float4 p0 = *(const float4*)&es_attr[(size_t)e * 8];
        float4 p1 = *(const float4*)&es_attr[(size_t)e * 8 + 4];
        es[0] = p0.x; es[1] = p0.y; es[2] = p0.z; es[3] = p0.w;
        es[4] = p1.x; es[5] = p1.y; es[6] = p1.z; es[7] = p1.w;
    }
    float h1[64];
    #pragma unroll
    for (int k = 0; k < 64; k += 4) {
        float ax = 0.f, ay = 0.f, az = 0.f, aw = 0.f;
        #pragma unroll
        for (int j = 0; j < 8; j++) {
            float4 w = *(const float4*)&sM1[j * 64 + k];
            ax = fmaf(es[j], w.x, ax); ay = fmaf(es[j], w.y, ay);
            az = fmaf(es[j], w.z, az); aw = fmaf(es[j], w.w, aw);
        }
        h1[k + 0] = gelu_tanh(ax); h1[k + 1] = gelu_tanh(ay);
        h1[k + 2] = gelu_tanh(az); h1[k + 3] = gelu_tanh(aw);
    }
    #pragma unroll
    for (int k = 0; k < 64; k += 4) {
        float ax = 0.f, ay = 0.f, az = 0.f, aw = 0.f;
        #pragma unroll
        for (int j = 0; j < 64; j++) {
            float4 w = *(const float4*)&sM2[j * 64 + k];
            ax = fmaf(h1[j], w.x, ax); ay = fmaf(h1[j], w.y, ay);
            az = fmaf(h1[j], w.z, az); aw = fmaf(h1[j], w.w, aw);
        }
        *(float4*)&hout[k] = make_float4(gelu_tanh(ax), gelu_tanh(ay),
                                         gelu_tanh(az), gelu_tanh(aw));
    }
}

// ---------------- kernel 3: mma.sync w-GEMM + TP + scatter ----------------
// grid (1250, 3): 128-edge tile x 128-col segment. block 256 = 8 warps (4x2 warp grid).
// bf16x3 split precision: D = Ah*Bh + Ah*Bl + Al*Bh (fp32 accumulate).
// smem: staging A/B bf16 (64KB, SW128-swizzled) reused as acc dump [128][132] f32.
#define OFF_AHI  0
#define OFF_ALO  16384
#define OFF_BHI  32768
#define OFF_BLO  49152
#define OFF_SRC  67584
#define OFF_DST  68096
#define OFF_Y    68608
#define SMEM_MMA 70656
#define ACC_STRIDE 132

__global__ __launch_bounds__(256, 2)
void edge_mma_kernel(const float* __restrict__ edge_attr,
                     const int* __restrict__ edge_src,
                     const int* __restrict__ edge_dst) {
    extern __shared__ char smc[];
    const uint32_t sb = smem_u32(smc);
    const int tid = threadIdx.x;
    const int wid = tid >> 5;
    const int lane = tid & 31;
    const int seg = blockIdx.y;
    const int B = blockIdx.x * 128;

    int* sSrc = (int*)(smc + OFF_SRC);
    int* sDst = (int*)(smc + OFF_DST);
    float4* sY = (float4*)(smc + OFF_Y);

    // ---- stage A: g_h tile [128][64] f32 -> bf16 hi/lo, swizzled ----
    for (int i = tid; i < 2048; i += 256) {
        int row = i >> 4, c4 = i & 15;   // float4 index within row
        float4 v = *(const float4*)&g_h[(size_t)(B + row) * 64 + c4 * 4];
        __nv_bfloat162 h0, h1, l0, l1;
        h0.x = __float2bfloat16(v.x); h0.y = __float2bfloat16(v.y);
        h1.x = __float2bfloat16(v.z); h1.y = __float2bfloat16(v.w);
        l0.x = __float2bfloat16(v.x - __bfloat162float(h0.x));
        l0.y = __float2bfloat16(v.y - __bfloat162float(h0.y));
        l1.x = __float2bfloat16(v.z - __bfloat162float(h1.x));
        l1.y = __float2bfloat16(v.w - __bfloat162float(h1.y));
        uint32_t off = row * 128 + (c4 >> 1) * 16;
        uint32_t sub = (c4 & 1) * 8;
        uint32_t sw = swz(off) + sub;
        *(uint2*)(smc + OFF_AHI + sw) = make_uint2(*(uint32_t*)&h0, *(uint32_t*)&h1);
        *(uint2*)(smc + OFF_ALO + sw) = make_uint2(*(uint32_t*)&l0, *(uint32_t*)&l1);
    }
    // ---- stage B: Wt segment [128][64] bf16 hi/lo, swizzled ----
    for (int i = tid; i < 1024; i += 256) {
        int row = i >> 3, c = i & 7;
        uint32_t sw = swz(row * 128 + c * 16);
        *(uint4*)(smc + OFF_BHI + sw) =
            ((const uint4*)(g_Wt_hi + (size_t)(seg * 128 + row) * 64))[c];
        *(uint4*)(smc + OFF_BLO + sw) =
            ((const uint4*)(g_Wt_lo + (size_t)(seg * 128 + row) * 64))[c];
    }
    // ---- edge metadata ----
    if (tid < 128) {
        int e = B + tid;
        sSrc[tid] = edge_src[e];
        sDst[tid] = edge_dst[e];
        sY[tid] = *(const float4*)&edge_attr[(size_t)e * 4];
    }
    __syncthreads();

    // ---- MMA: warp (wm 0-3: 32 edges, wn 0-1: 64 cols) ----
    const int wm = wid & 3, wn = wid >> 2;
    const int g = lane >> 2, t4 = lane & 3;
    const int lrow = (lane & 7) + ((lane >> 3) & 1) * 8;
    const int lk16 = ((lane >> 4) & 1) * 16;

    float acc[2][8][4];
    #pragma unroll
    for (int fm = 0; fm < 2; fm++)
        #pragma unroll
        for (int fn = 0; fn < 8; fn++)
            #pragma unroll
            for (int q = 0; q < 4; q++) acc[fm][fn][q] = 0.f;

    #pragma unroll
    for (int pass = 0; pass < 3; pass++) {
        const uint32_t aBase = sb + ((pass == 2) ? OFF_ALO : OFF_AHI);
        const uint32_t bBase = sb + ((pass == 1) ? OFF_BLO : OFF_BHI);
        #pragma unroll
        for (int ks = 0; ks < 4; ks++) {
            uint32_t a[2][4];
            #pragma unroll
            for (int fm = 0; fm < 2; fm++) {
                uint32_t off = (wm * 32 + fm * 16 + lrow) * 128 + ks * 32 + lk16;
                ldsm4(a[fm], aBase + swz(off));
            }
            uint32_t b[4][4];
            #pragma unroll
            for (int nf = 0; nf < 4; nf++) {
                uint32_t off = (wn * 64 + nf * 16 + lrow) * 128 + ks * 32 + lk16;
                ldsm4(b[nf], bBase + swz(off));
            }
            #pragma unroll
            for (int fm = 0; fm < 2; fm++)
                #pragma unroll
                for (int nf = 0; nf < 4; nf++) {
                    mma_bf16(acc[fm][nf * 2 + 0], a[fm], b[nf][0], b[nf][2]);
                    mma_bf16(acc[fm][nf * 2 + 1], a[fm], b[nf][1], b[nf][3]);
                }
        }
    }

    // ---- dump acc to smem (reuses staging area) ----
    __syncthreads();
    float* accS = (float*)smc;   // [128][ACC_STRIDE]
    #pragma unroll
    for (int fm = 0; fm < 2; fm++) {
        #pragma unroll
        for (int fn = 0; fn < 8; fn++) {
            int row = wm * 32 + fm * 16 + g;
            int col = wn * 64 + fn * 8 + 2 * t4;
            *(float2*)&accS[row * ACC_STRIDE + col] =
                make_float2(acc[fm][fn][0], acc[fm][fn][1]);
            *(float2*)&accS[(row + 8) * ACC_STRIDE + col] =
                make_float2(acc[fm][fn][2], acc[fm][fn][3]);
        }
    }
    __syncthreads();

    // ---- epilogue: thread = (edge, col-half); red4 scatter ----
    const int e = tid & 127;
    const int half = tid >> 7;
    const float* fr = g_feat + (size_t)sSrc[e] * 320;
    float* ar = g_agg + (size_t)sDst[e] * 768;
    float4 yv = sY[e];   // y0 = yv.x ; y1 = (yv.y, yv.z, yv.w)

    #pragma unroll
    for (int q = 0; q < 16; q++) {
        const int l = half * 64 + q * 4;    // local col within segment
        float4 wv = *(const float4*)&accS[e * ACC_STRIDE + l];
        float w0 = wv.x, w1 = wv.y, w2 = wv.z, w3 = wv.w;
        if (seg == 0) {                    // mid0a = w * e0 * y0
            float4 e0v = *(const float4*)(fr + l);
            red4(ar + l, w0 * e0v.x * yv.x, w1 * e0v.y * yv.x,
                         w2 * e0v.z * yv.x, w3 * e0v.w * yv.x);
        } else if (seg == 1) {             // mid1a = w * e0 * y1_i (SoA)
            float4 e0v = *(const float4*)(fr + l);
            float t0 = w0 * e0v.x, t1 = w1 * e0v.y, t2 = w2 * e0v.z, t3 = w3 * e0v.w;
            red4(ar + 192 + l,       t0 * yv.y, t1 * yv.y, t2 * yv.y, t3 * yv.y);
            red4(ar + 192 + 128 + l, t0 * yv.z, t1 * yv.z, t2 * yv.z, t3 * yv.z);
            red4(ar + 192 + 256 + l, t0 * yv.w, t1 * yv.w, t2 * yv.w, t3 * yv.w);
        } else if (l < 64) {               // mid1b = w * e1_i * y0 (SoA)
            const float* p = fr + 128 + 3 * l;
            float4 a = *(const float4*)p;
            float4 b = *(const float4*)(p + 4);
            float4 c = *(const float4*)(p + 8);
            float y0 = yv.x;
            red4(ar + 576 + l,       w0 * a.x * y0, w1 * a.w * y0, w2 * b.z * y0, w3 * c.y * y0);
            red4(ar + 576 + 64 + l,  w0 * a.y * y0, w1 * b.x * y0, w2 * b.w * y0, w3 * c.z * y0);
            red4(ar + 576 + 128 + l, w0 * a.z * y0, w1 * b.y * y0, w2 * c.x * y0, w3 * c.w * y0);
        } else {                           // mid0b = w * dot(e1, y1)
            const int u = l - 64;
            const float* p = fr + 128 + 3 * u;
            float4 a = *(const float4*)p;
            float4 b = *(const float4*)(p + 4);
            float4 c = *(const float4*)(p + 8);
            float d0 = a.x * yv.y + a.y * yv.z + a.z * yv.w;
            float d1 = a.w * yv.y + b.x * yv.z + b.y * yv.w;
            float d2 = b.z * yv.y + b.w * yv.z + c.x * yv.w;
            float d3 = c.y * yv.y + c.z * yv.z + c.w * yv.w;
            red4(ar + 128 + u, w0 * d0, w1 * d1, w2 * d2, w3 * d3);
        }
    }
}

// ---------------- kernel 4: node post (streaming-W GEMMs + combine) ----------------
__global__ __launch_bounds__(256) void node_post_kernel(const float* __restrict__ Wo0,
                                 const float* __restrict__ Wo1,
                                 float* __restrict__ out) {
    extern __shared__ float sm[];
    const int tid = threadIdx.x;
    const float so = 0.3826834323650898f * 0.07216878364870323f; // sin(pi/8)/sqrt(192)

    if (blockIdx.x < 625) {
        const int nb = blockIdx.x * 16;
        float* zs = sm;                    // 16 x 192
        for (int idx = tid; idx < 16 * 192; idx += 256)
            zs[idx] = g_agg[(size_t)(nb + idx / 192) * 768 + (idx % 192)];
        __syncthreads();

        const int nh = tid >> 7;
        const int u  = tid & 127;
        float acc[8];
        #pragma unroll
        for (int n = 0; n < 8; n++) acc[n] = 0.f;
        #pragma unroll 2
        for (int v = 0; v < 192; v += 4) {
            float w0 = Wo0[(v + 0) * 128 + u];
            float w1 = Wo0[(v + 1) * 128 + u];
            float w2 = Wo0[(v + 2) * 128 + u];
            float w3 = Wo0[(v + 3) * 128 + u];
            #pragma unroll
            for (int n = 0; n < 8; n++) {
                float4 zq = *(const float4*)&zs[(nh * 8 + n) * 192 + v];
                acc[n] = fmaf(zq.x, w0, acc[n]);
                acc[n] = fmaf(zq.y, w1, acc[n]);
                acc[n] = fmaf(zq.z, w2, acc[n]);
                acc[n] = fmaf(zq.w, w3, acc[n]);
            }
        }
        #pragma unroll
        for (int n = 0; n < 8; n++) {
            size_t o = (size_t)(nb + nh * 8 + n) * 320 + u;
            out[o] = g_self[o] + acc[n] * so;
        }
    } else {
        const int nb = (blockIdx.x - 625) * 16;
        float* zs = sm;                    // 16 x 3 x 192
        for (int idx = tid; idx < 16 * 576; idx += 256) {
            int n = idx / 576, r = idx % 576;
            int i = r / 192, v = r % 192;
            size_t base = (size_t)(nb + n) * 768;
            zs[idx] = (v < 128) ? g_agg[base + 192 + i * 128 + v]
                                : g_agg[base + 576 + i * 64 + (v - 128)];
        }
        __syncthreads();

        const int nq = tid >> 6;
        const int u  = tid & 63;
        float acc[4][3];
        #pragma unroll
        for (int n = 0; n < 4; n++)
            #pragma unroll
            for (int i = 0; i < 3; i++) acc[n][i] = 0.f;
        #pragma unroll 2
        for (int v = 0; v < 192; v += 4) {
            float w0 = Wo1[(v + 0) * 64 + u];
            float w1 = Wo1[(v + 1) * 64 + u];
            float w2 = Wo1[(v + 2) * 64 + u];
            float w3 = Wo1[(v + 3) * 64 + u];
            #pragma unroll
            for (int n = 0; n < 4; n++) {
                const float* zb = &zs[(nq * 4 + n) * 576 + v];
                #pragma unroll
                for (int i = 0; i < 3; i++) {
                    float4 zq = *(const float4*)&zb[i * 192];
                    acc[n][i] = fmaf(zq.x, w0, acc[n][i]);
                    acc[n][i] = fmaf(zq.y, w1, acc[n][i]);
                    acc[n][i] = fmaf(zq.z, w2, acc[n][i]);
                    acc[n][i] = fmaf(zq.w, w3, acc[n][i]);
                }
            }
        }
        #pragma unroll
        for (int n = 0; n < 4; n++)
            #pragma unroll
            for (int i = 0; i < 3; i++) {
                size_t o = (size_t)(nb + nq * 4 + n) * 320 + 128 + u * 3 + i;
                out[o] = g_self[o] + acc[n][i] * so;
            }
    }
}

// ---------------- launch ----------------
extern "C" void kernel_launch(void* const* d_in, const int* in_sizes, int n_in,
                              void* d_out, int out_size) {
    const float* node_input = (const float*)d_in[0];
    const float* edge_attr  = (const float*)d_in[1];
    const float* edge_sc    = (const float*)d_in[2];
    const float* Wa0 = (const float*)d_in[3];
    const float* Wa1 = (const float*)d_in[4];
    const float* Wb0 = (const float*)d_in[5];
    const float* Wb1 = (const float*)d_in[6];
    const float* M1  = (const float*)d_in[7];
    const float* M2  = (const float*)d_in[8];
    const float* Wtp0 = (const float*)d_in[9];
    const float* Wtp1 = (const float*)d_in[10];
    const float* Wtp2 = (const float*)d_in[11];
    const float* Wtp3 = (const float*)d_in[12];
    const float* Wo0  = (const float*)d_in[13];
    const float* Wo1  = (const float*)d_in[14];
    const int* esrc = (const int*)d_in[15];
    const int* edst = (const int*)d_in[16];
    float* out = (float*)d_out;

    cudaFuncSetAttribute(edge_mma_kernel,  cudaFuncAttributeMaxDynamicSharedMemorySize, SMEM_MMA);
    cudaFuncSetAttribute(node_post_kernel, cudaFuncAttributeMaxDynamicSharedMemorySize, 36864);

    node_pre_kernel<<<1250 + ZERO_BLK, 256, 12288>>>(node_input, Wa0, Wa1, Wb0, Wb1);
    wt_prep_kernel<<<96, 256>>>(Wtp0, Wtp1, Wtp2, Wtp3);
    edge_mlp_kernel<<<625, 256>>>(edge_sc, M1, M2);
    edge_mma_kernel<<<dim3(1250, 3), 256, SMEM_MMA>>>(edge_attr, esrc, edst);
    node_post_kernel<<<1250, 256, 36864>>>(Wo0, Wo1, out);
}